// round 6
// baseline (speedup 1.0000x reference)
#include <cuda_runtime.h>
#include <cuda_fp16.h>

#define BB 256
#define RR 2592
#define LL 32
#define CC 16
#define BL 8192           // BB*LL
#define RL 82944          // RR*LL
#define RCH 72            // r-chunk for s-kernels
#define UHAT_ELEMS (RR*BB*LL)

// Scratch (device globals: no allocation in kernel_launch; zero-initialized)
__device__ __half g_uhat[UHAT_ELEMS];  // layout [r][b][l], fp16, 42.5 MB
__device__ float g_s[BL];
__device__ float g_c[RR];
__device__ float g_blog[RR];
__device__ float g_a[RR];

__device__ __forceinline__ float squashf(float s) {
    float sq = s * s;
    return sq * s / ((1.0f + sq) * sqrtf(sq));
}

// ---------------------------------------------------------------------------
// u_hat[r,b,l] = sum_c W[r,l,c] * x[b,r,c]; one block per r. fp16 store.
// Blocks 0/1 also re-init routing state for this graph replay (no sync needed:
// later kernels are ordered by launch boundaries).
__global__ __launch_bounds__(256) void k_uhat(const float* __restrict__ x,
                                              const float* __restrict__ W) {
    __shared__ float4 xs4[BB * 4];      // x[:, r, :] as float4 rows, 16 KB
    __shared__ float  Ws[32 * 17];
    const int r = blockIdx.x;
    const int t = threadIdx.x;

    if (r == 0) {
        #pragma unroll
        for (int k = 0; k < 32; k++) g_s[t + k * 256] = 0.0f;
    } else if (r == 1) {
        for (int i = t; i < RR; i += 256) { g_blog[i] = 0.0f; g_c[i] = 1.0f / (float)RR; }
    }

    for (int i = t; i < 512; i += 256) {
        int l = i >> 4, c = i & 15;
        Ws[l * 17 + c] = W[r * 512 + i];
    }
    const float4* x4 = (const float4*)x;
    #pragma unroll
    for (int k = 0; k < 4; k++) {
        int idx = k * 256 + t;           // idx = b*4 + c4
        int b = idx >> 2, c4 = idx & 3;
        xs4[idx] = x4[(b * RR + r) * 4 + c4];
    }
    __syncthreads();

    const int lane = t & 31, warp = t >> 5;
    float w[16];
    #pragma unroll
    for (int c = 0; c < 16; c++) w[c] = Ws[lane * 17 + c];

    #pragma unroll 4
    for (int it = 0; it < 32; it++) {
        int b = it * 8 + warp;
        float4 xa = xs4[b * 4 + 0];
        float4 xb = xs4[b * 4 + 1];
        float4 xc = xs4[b * 4 + 2];
        float4 xd = xs4[b * 4 + 3];
        float acc = w[0] * xa.x;
        acc = fmaf(w[1],  xa.y, acc);  acc = fmaf(w[2],  xa.z, acc);
        acc = fmaf(w[3],  xa.w, acc);  acc = fmaf(w[4],  xb.x, acc);
        acc = fmaf(w[5],  xb.y, acc);  acc = fmaf(w[6],  xb.z, acc);
        acc = fmaf(w[7],  xb.w, acc);  acc = fmaf(w[8],  xc.x, acc);
        acc = fmaf(w[9],  xc.y, acc);  acc = fmaf(w[10], xc.z, acc);
        acc = fmaf(w[11], xc.w, acc);  acc = fmaf(w[12], xd.x, acc);
        acc = fmaf(w[13], xd.y, acc);  acc = fmaf(w[14], xd.z, acc);
        acc = fmaf(w[15], xd.w, acc);
        g_uhat[(size_t)r * BL + b * LL + lane] = __float2half_rn(acc);
    }
}

// ---------------------------------------------------------------------------
// s[b,l] += sum_{r in chunk} c[r]*u_hat[r,b,l].
// Warp loads 512B contiguous per r (int4/lane over 8 b-rows). grid (4, 36).
__global__ __launch_bounds__(256) void k_s() {
    __shared__ float cs[RCH];
    const int t = threadIdx.x;
    const int r0 = blockIdx.y * RCH;
    if (t < RCH) cs[t] = g_c[r0 + t];
    __syncthreads();

    const int w = t >> 5, lane = t & 31;
    const int b = blockIdx.x * 64 + w * 8 + (lane >> 2);
    const int l8 = (lane & 3) * 8;
    const int4* u = (const int4*)g_uhat + (size_t)r0 * 1024 + b * 4 + (lane & 3);

    float a[8] = {0.f, 0.f, 0.f, 0.f, 0.f, 0.f, 0.f, 0.f};
    #pragma unroll 8
    for (int i = 0; i < RCH; i++) {
        int4 p = u[(size_t)i * 1024];
        const float cr = cs[i];
        const __half2* hp = (const __half2*)&p;
        #pragma unroll
        for (int j = 0; j < 4; j++) {
            float2 f = __half22float2(hp[j]);
            a[2 * j]     = fmaf(cr, f.x, a[2 * j]);
            a[2 * j + 1] = fmaf(cr, f.y, a[2 * j + 1]);
        }
    }
    float* sdst = g_s + b * LL + l8;
    #pragma unroll
    for (int j = 0; j < 8; j++) atomicAdd(sdst + j, a[j]);
}

// ---------------------------------------------------------------------------
// a[r] = mean_b sum_l u_hat[r,b,l]*squash(s)[b,l]; 8 r's per block, grid 324.
__global__ __launch_bounds__(256) void k_a() {
    __shared__ float vsm[BL];          // squash(s), 32 KB
    __shared__ float red[8][9];
    const int t = threadIdx.x;
    const int w = t >> 5, lane = t & 31;

    float4* s4 = (float4*)g_s;
    float4* v4 = (float4*)vsm;
    for (int i = t; i < BL / 4; i += 256) {
        float4 s = s4[i];
        float4 o;
        o.x = squashf(s.x); o.y = squashf(s.y);
        o.z = squashf(s.z); o.w = squashf(s.w);
        v4[i] = o;
    }
    __syncthreads();

    const int rbase = blockIdx.x * 8;
    for (int rr = 0; rr < 8; rr++) {
        const int4* u = (const int4*)g_uhat + (size_t)(rbase + rr) * 1024;
        float a[8] = {0.f, 0.f, 0.f, 0.f, 0.f, 0.f, 0.f, 0.f};
        #pragma unroll
        for (int j = 0; j < 4; j++) {
            int idx = j * 256 + t;
            int4 p = u[idx];
            const __half2* hp = (const __half2*)&p;
            float4 va = v4[idx * 2];
            float4 vb = v4[idx * 2 + 1];
            float2 f0 = __half22float2(hp[0]);
            float2 f1 = __half22float2(hp[1]);
            float2 f2 = __half22float2(hp[2]);
            float2 f3 = __half22float2(hp[3]);
            a[0] = fmaf(f0.x, va.x, a[0]);  a[1] = fmaf(f0.y, va.y, a[1]);
            a[2] = fmaf(f1.x, va.z, a[2]);  a[3] = fmaf(f1.y, va.w, a[3]);
            a[4] = fmaf(f2.x, vb.x, a[4]);  a[5] = fmaf(f2.y, vb.y, a[5]);
            a[6] = fmaf(f3.x, vb.z, a[6]);  a[7] = fmaf(f3.y, vb.w, a[7]);
        }
        float s = ((a[0] + a[1]) + (a[2] + a[3])) + ((a[4] + a[5]) + (a[6] + a[7]));
        #pragma unroll
        for (int o = 16; o; o >>= 1) s += __shfl_xor_sync(0xffffffffu, s, o);
        if (lane == 0) red[rr][w] = s;
    }
    __syncthreads();
    if (t < 64) {
        int rr = t >> 3, ww = t & 7;
        float v = red[rr][ww];
        v += __shfl_xor_sync(0xffffffffu, v, 1);
        v += __shfl_xor_sync(0xffffffffu, v, 2);
        v += __shfl_xor_sync(0xffffffffu, v, 4);
        if (ww == 0) g_a[rbase + rr] = v * (1.0f / (float)BB);
    }
}

// ---------------------------------------------------------------------------
// b += a ; c = softmax(b); zero g_s for the next routing iteration.
// Single block, 1024 threads.
__global__ __launch_bounds__(1024) void k_update() {
    __shared__ float red[32];
    const int t = threadIdx.x;
    float vals[3];
    float mx = -1e30f;
    #pragma unroll
    for (int k = 0; k < 3; k++) {
        int i = t + k * 1024;
        if (i < RR) {
            float bn = g_blog[i] + g_a[i];
            g_blog[i] = bn;
            vals[k] = bn;
            mx = fmaxf(mx, bn);
        } else vals[k] = -1e30f;
    }
    #pragma unroll
    for (int k = 0; k < 8; k++) g_s[t + k * 1024] = 0.0f;

    #pragma unroll
    for (int o = 16; o; o >>= 1) mx = fmaxf(mx, __shfl_xor_sync(0xffffffffu, mx, o));
    if ((t & 31) == 0) red[t >> 5] = mx;
    __syncthreads();
    if (t < 32) {
        float m = red[t];
        #pragma unroll
        for (int o = 16; o; o >>= 1) m = fmaxf(m, __shfl_xor_sync(0xffffffffu, m, o));
        if (t == 0) red[0] = m;
    }
    __syncthreads();
    const float bmax = red[0];
    __syncthreads();

    float ex[3];
    float es = 0.0f;
    #pragma unroll
    for (int k = 0; k < 3; k++) {
        int i = t + k * 1024;
        ex[k] = (i < RR) ? expf(vals[k] - bmax) : 0.0f;
        es += ex[k];
    }
    #pragma unroll
    for (int o = 16; o; o >>= 1) es += __shfl_xor_sync(0xffffffffu, es, o);
    if ((t & 31) == 0) red[t >> 5] = es;
    __syncthreads();
    if (t < 32) {
        float s = red[t];
        #pragma unroll
        for (int o = 16; o; o >>= 1) s += __shfl_xor_sync(0xffffffffu, s, o);
        if (t == 0) red[0] = s;
    }
    __syncthreads();
    const float inv = 1.0f / red[0];
    #pragma unroll
    for (int k = 0; k < 3; k++) {
        int i = t + k * 1024;
        if (i < RR) g_c[i] = ex[k] * inv;
    }
}

// ---------------------------------------------------------------------------
// Final iteration fused: u_out[b,r,l] = c[r]*u_hat[r,b,l] written to out,
// s accumulated via atomics. (v written by k_vout afterwards.)
__global__ __launch_bounds__(256) void k_s_out(float* __restrict__ out) {
    __shared__ float cs[RCH];
    const int t = threadIdx.x;
    const int r0 = blockIdx.y * RCH;
    if (t < RCH) cs[t] = g_c[r0 + t];
    __syncthreads();

    const int w = t >> 5, lane = t & 31;
    const int b = blockIdx.x * 64 + w * 8 + (lane >> 2);
    const int l8 = (lane & 3) * 8;
    const int4* u = (const int4*)g_uhat + (size_t)r0 * 1024 + b * 4 + (lane & 3);
    float* uo = out + BL + b * RL + l8;

    float a[8] = {0.f, 0.f, 0.f, 0.f, 0.f, 0.f, 0.f, 0.f};
    #pragma unroll 4
    for (int i = 0; i < RCH; i++) {
        int4 p = u[(size_t)i * 1024];
        const float cr = cs[i];
        const __half2* hp = (const __half2*)&p;
        float2 f0 = __half22float2(hp[0]);
        float2 f1 = __half22float2(hp[1]);
        float2 f2 = __half22float2(hp[2]);
        float2 f3 = __half22float2(hp[3]);
        float4 o1, o2;
        o1.x = cr * f0.x;  o1.y = cr * f0.y;
        o1.z = cr * f1.x;  o1.w = cr * f1.y;
        o2.x = cr * f2.x;  o2.y = cr * f2.y;
        o2.z = cr * f3.x;  o2.w = cr * f3.y;
        a[0] += o1.x; a[1] += o1.y; a[2] += o1.z; a[3] += o1.w;
        a[4] += o2.x; a[5] += o2.y; a[6] += o2.z; a[7] += o2.w;
        float* dst = uo + (r0 + i) * LL;
        ((float4*)dst)[0] = o1;
        ((float4*)dst)[1] = o2;
    }
    float* sdst = g_s + b * LL + l8;
    #pragma unroll
    for (int j = 0; j < 8; j++) atomicAdd(sdst + j, a[j]);
}

// ---------------------------------------------------------------------------
// v_out = squash(s) into out[0:8192].
__global__ __launch_bounds__(256) void k_vout(float* __restrict__ out) {
    int i = blockIdx.x * 256 + threadIdx.x;
    out[i] = squashf(g_s[i]);
}

// ---------------------------------------------------------------------------
extern "C" void kernel_launch(void* const* d_in, const int* in_sizes, int n_in,
                              void* d_out, int out_size) {
    const float* x = (const float*)d_in[0];   // (B, R, C)
    const float* W = (const float*)d_in[1];   // (1, R, 1, L, C)
    float* out = (float*)d_out;

    k_uhat<<<RR, 256>>>(x, W);            // + state init
    k_s<<<dim3(4, 36), 256>>>();          // it 0
    k_a<<<324, 256>>>();                  // it 0
    k_update<<<1, 1024>>>();              // softmax + zero s
    k_s<<<dim3(4, 36), 256>>>();          // it 1
    k_a<<<324, 256>>>();                  // it 1
    k_update<<<1, 1024>>>();              // softmax + zero s
    k_s_out<<<dim3(4, 36), 256>>>(out);   // it 2 + u_out
    k_vout<<<32, 256>>>(out);             // v_out
}

// round 7
// speedup vs baseline: 1.0918x; 1.0918x over previous
#include <cuda_runtime.h>
#include <cuda_fp16.h>

#define BB 256
#define RR 2592
#define LL 32
#define BL 8192           // BB*LL
#define RL 82944          // RR*LL
#define RCH 36            // r-chunk for s-kernels
#define GY  72            // RR/RCH
#define UHAT_ELEMS (RR*BB*LL)

// Scratch (device globals: no allocation in kernel_launch)
__device__ __half g_uhat[UHAT_ELEMS];  // layout [r][b][l], fp16, 42.5 MB
__device__ float g_s0[BL];
__device__ float g_s1[BL];
__device__ float g_s2[BL];
__device__ float g_a0[RR];
__device__ float g_a1[RR];

// squash(s) = s^2*s / ((1+s^2)*sqrt(s^2)) = s*|s| / (1+s^2)
__device__ __forceinline__ float squashf(float s) {
    return __fdividef(s * fabsf(s), 1.0f + s * s);
}

// ---------------------------------------------------------------------------
// u_hat[r,b,l] = sum_c W[r,l,c] * x[b,r,c]; one block per r. fp16 store.
// Blocks 0/1 also re-init scratch for this graph replay.
__global__ __launch_bounds__(256) void k_uhat(const float* __restrict__ x,
                                              const float* __restrict__ W) {
    __shared__ float4 xs4[BB * 4];      // x[:, r, :] as float4 rows, 16 KB
    __shared__ float  Ws[32 * 17];
    const int r = blockIdx.x;
    const int t = threadIdx.x;

    if (r == 0) {
        #pragma unroll
        for (int k = 0; k < 32; k++) {
            g_s0[t + k * 256] = 0.0f;
            g_s1[t + k * 256] = 0.0f;
            g_s2[t + k * 256] = 0.0f;
        }
    } else if (r == 1) {
        for (int i = t; i < RR; i += 256) g_a1[i] = 0.0f;
    }

    for (int i = t; i < 512; i += 256) {
        int l = i >> 4, c = i & 15;
        Ws[l * 17 + c] = W[r * 512 + i];
    }
    const float4* x4 = (const float4*)x;
    #pragma unroll
    for (int k = 0; k < 4; k++) {
        int idx = k * 256 + t;           // idx = b*4 + c4
        int b = idx >> 2, c4 = idx & 3;
        xs4[idx] = x4[(b * RR + r) * 4 + c4];
    }
    __syncthreads();

    const int lane = t & 31, warp = t >> 5;
    float w[16];
    #pragma unroll
    for (int c = 0; c < 16; c++) w[c] = Ws[lane * 17 + c];

    #pragma unroll 4
    for (int it = 0; it < 32; it++) {
        int b = it * 8 + warp;
        float4 xa = xs4[b * 4 + 0];
        float4 xb = xs4[b * 4 + 1];
        float4 xc = xs4[b * 4 + 2];
        float4 xd = xs4[b * 4 + 3];
        float acc = w[0] * xa.x;
        acc = fmaf(w[1],  xa.y, acc);  acc = fmaf(w[2],  xa.z, acc);
        acc = fmaf(w[3],  xa.w, acc);  acc = fmaf(w[4],  xb.x, acc);
        acc = fmaf(w[5],  xb.y, acc);  acc = fmaf(w[6],  xb.z, acc);
        acc = fmaf(w[7],  xb.w, acc);  acc = fmaf(w[8],  xc.x, acc);
        acc = fmaf(w[9],  xc.y, acc);  acc = fmaf(w[10], xc.z, acc);
        acc = fmaf(w[11], xc.w, acc);  acc = fmaf(w[12], xd.x, acc);
        acc = fmaf(w[13], xd.y, acc);  acc = fmaf(w[14], xd.z, acc);
        acc = fmaf(w[15], xd.w, acc);
        g_uhat[(size_t)r * BL + b * LL + lane] = __float2half_rn(acc);
    }
}

// ---------------------------------------------------------------------------
// Per-block softmax over (g_a0 + g_a1): fills cs[0..RCH) for chunk r0.
// All blocks compute identical reductions (deterministic).
__device__ __forceinline__ void block_softmax(float* cs, int r0, int t) {
    __shared__ float red[8];
    const int w = t >> 5, lane = t & 31;
    float mx = -1e30f;
    for (int i = t; i < RR; i += 256)
        mx = fmaxf(mx, g_a0[i] + g_a1[i]);
    #pragma unroll
    for (int o = 16; o; o >>= 1) mx = fmaxf(mx, __shfl_xor_sync(0xffffffffu, mx, o));
    if (lane == 0) red[w] = mx;
    __syncthreads();
    mx = red[0];
    #pragma unroll
    for (int j = 1; j < 8; j++) mx = fmaxf(mx, red[j]);
    __syncthreads();

    float es = 0.0f;
    for (int i = t; i < RR; i += 256)
        es += __expf(g_a0[i] + g_a1[i] - mx);
    #pragma unroll
    for (int o = 16; o; o >>= 1) es += __shfl_xor_sync(0xffffffffu, es, o);
    if (lane == 0) red[w] = es;
    __syncthreads();
    es = red[0];
    #pragma unroll
    for (int j = 1; j < 8; j++) es += red[j];
    const float inv = 1.0f / es;
    if (t < RCH) cs[t] = __expf(g_a0[r0 + t] + g_a1[r0 + t] - mx) * inv;
    __syncthreads();
}

// ---------------------------------------------------------------------------
// Core s-accumulation: sbuf[b,l] += sum_{i<RCH} cs[i]*u_hat[r0+i,b,l].
// Warp loads 512B contiguous per r (int4/lane over 8 b-rows).
__device__ __forceinline__ void s_accum(const float* cs, int r0, int bx, int t,
                                        float* sbuf) {
    const int w = t >> 5, lane = t & 31;
    const int b = bx * 64 + w * 8 + (lane >> 2);
    const int l8 = (lane & 3) * 8;
    const int4* u = (const int4*)g_uhat + (size_t)r0 * 1024 + b * 4 + (lane & 3);

    float a[8] = {0.f, 0.f, 0.f, 0.f, 0.f, 0.f, 0.f, 0.f};
    #pragma unroll 4
    for (int i = 0; i < RCH; i++) {
        int4 p = u[(size_t)i * 1024];
        const float cr = cs[i];
        const __half2* hp = (const __half2*)&p;
        #pragma unroll
        for (int j = 0; j < 4; j++) {
            float2 f = __half22float2(hp[j]);
            a[2 * j]     = fmaf(cr, f.x, a[2 * j]);
            a[2 * j + 1] = fmaf(cr, f.y, a[2 * j + 1]);
        }
    }
    float* sdst = sbuf + b * LL + l8;
    #pragma unroll
    for (int j = 0; j < 8; j++) atomicAdd(sdst + j, a[j]);
}

// it0: c uniform = 1/RR — no softmax needed.
__global__ __launch_bounds__(256) void k_s0() {
    __shared__ float cs[RCH];
    const int t = threadIdx.x;
    if (t < RCH) cs[t] = 1.0f / (float)RR;
    __syncthreads();
    s_accum(cs, blockIdx.y * RCH, blockIdx.x, t, g_s0);
}

// it1: c = softmax(a0)  (g_a1 is zero here)
__global__ __launch_bounds__(256) void k_s1() {
    __shared__ float cs[RCH];
    const int t = threadIdx.x;
    const int r0 = blockIdx.y * RCH;
    block_softmax(cs, r0, t);
    s_accum(cs, r0, blockIdx.x, t, g_s1);
}

// ---------------------------------------------------------------------------
// a[r] = mean_b sum_l u_hat[r,b,l]*squash(s)[b,l]; 8 r's per block, grid 324.
template<int IT>
__global__ __launch_bounds__(256) void k_a() {
    __shared__ float vsm[BL];          // squash(s), 32 KB
    __shared__ float red[8][9];
    const int t = threadIdx.x;
    const int w = t >> 5, lane = t & 31;
    const float* sbuf = (IT == 0) ? g_s0 : g_s1;
    float* abuf = (IT == 0) ? g_a0 : g_a1;

    const float4* s4 = (const float4*)sbuf;
    float4* v4 = (float4*)vsm;
    for (int i = t; i < BL / 4; i += 256) {
        float4 s = s4[i];
        float4 o;
        o.x = squashf(s.x); o.y = squashf(s.y);
        o.z = squashf(s.z); o.w = squashf(s.w);
        v4[i] = o;
    }
    __syncthreads();

    const int rbase = blockIdx.x * 8;
    for (int rr = 0; rr < 8; rr++) {
        const int4* u = (const int4*)g_uhat + (size_t)(rbase + rr) * 1024;
        float a[8] = {0.f, 0.f, 0.f, 0.f, 0.f, 0.f, 0.f, 0.f};
        #pragma unroll
        for (int j = 0; j < 4; j++) {
            int idx = j * 256 + t;
            int4 p = u[idx];
            const __half2* hp = (const __half2*)&p;
            float4 va = v4[idx * 2];
            float4 vb = v4[idx * 2 + 1];
            float2 f0 = __half22float2(hp[0]);
            float2 f1 = __half22float2(hp[1]);
            float2 f2 = __half22float2(hp[2]);
            float2 f3 = __half22float2(hp[3]);
            a[0] = fmaf(f0.x, va.x, a[0]);  a[1] = fmaf(f0.y, va.y, a[1]);
            a[2] = fmaf(f1.x, va.z, a[2]);  a[3] = fmaf(f1.y, va.w, a[3]);
            a[4] = fmaf(f2.x, vb.x, a[4]);  a[5] = fmaf(f2.y, vb.y, a[5]);
            a[6] = fmaf(f3.x, vb.z, a[6]);  a[7] = fmaf(f3.y, vb.w, a[7]);
        }
        float s = ((a[0] + a[1]) + (a[2] + a[3])) + ((a[4] + a[5]) + (a[6] + a[7]));
        #pragma unroll
        for (int o = 16; o; o >>= 1) s += __shfl_xor_sync(0xffffffffu, s, o);
        if (lane == 0) red[rr][w] = s;
    }
    __syncthreads();
    if (t < 64) {
        int rr = t >> 3, ww = t & 7;
        float v = red[rr][ww];
        v += __shfl_xor_sync(0xffffffffu, v, 1);
        v += __shfl_xor_sync(0xffffffffu, v, 2);
        v += __shfl_xor_sync(0xffffffffu, v, 4);
        if (ww == 0) abuf[rbase + rr] = v * (1.0f / (float)BB);
    }
}

// ---------------------------------------------------------------------------
// Final iteration fused: c2 = softmax(a0+a1) per block; writes
// u_out[b,r,l] = c2[r]*u_hat[r,b,l] and accumulates s2 via atomics.
__global__ __launch_bounds__(256) void k_s_out(float* __restrict__ out) {
    __shared__ float cs[RCH];
    const int t = threadIdx.x;
    const int r0 = blockIdx.y * RCH;
    block_softmax(cs, r0, t);

    const int w = t >> 5, lane = t & 31;
    const int b = blockIdx.x * 64 + w * 8 + (lane >> 2);
    const int l8 = (lane & 3) * 8;
    const int4* u = (const int4*)g_uhat + (size_t)r0 * 1024 + b * 4 + (lane & 3);
    float* uo = out + BL + b * RL + l8;

    float a[8] = {0.f, 0.f, 0.f, 0.f, 0.f, 0.f, 0.f, 0.f};
    #pragma unroll 4
    for (int i = 0; i < RCH; i++) {
        int4 p = u[(size_t)i * 1024];
        const float cr = cs[i];
        const __half2* hp = (const __half2*)&p;
        float2 f0 = __half22float2(hp[0]);
        float2 f1 = __half22float2(hp[1]);
        float2 f2 = __half22float2(hp[2]);
        float2 f3 = __half22float2(hp[3]);
        float4 o1, o2;
        o1.x = cr * f0.x;  o1.y = cr * f0.y;
        o1.z = cr * f1.x;  o1.w = cr * f1.y;
        o2.x = cr * f2.x;  o2.y = cr * f2.y;
        o2.z = cr * f3.x;  o2.w = cr * f3.y;
        a[0] += o1.x; a[1] += o1.y; a[2] += o1.z; a[3] += o1.w;
        a[4] += o2.x; a[5] += o2.y; a[6] += o2.z; a[7] += o2.w;
        float* dst = uo + (r0 + i) * LL;
        ((float4*)dst)[0] = o1;
        ((float4*)dst)[1] = o2;
    }
    float* sdst = g_s2 + b * LL + l8;
    #pragma unroll
    for (int j = 0; j < 8; j++) atomicAdd(sdst + j, a[j]);
}

// ---------------------------------------------------------------------------
// v_out = squash(s2) into out[0:8192].
__global__ __launch_bounds__(256) void k_vout(float* __restrict__ out) {
    int i = blockIdx.x * 256 + threadIdx.x;
    out[i] = squashf(g_s2[i]);
}

// ---------------------------------------------------------------------------
extern "C" void kernel_launch(void* const* d_in, const int* in_sizes, int n_in,
                              void* d_out, int out_size) {
    const float* x = (const float*)d_in[0];   // (B, R, C)
    const float* W = (const float*)d_in[1];   // (1, R, 1, L, C)
    float* out = (float*)d_out;

    k_uhat<<<RR, 256>>>(x, W);                 // + scratch init
    k_s0<<<dim3(4, GY), 256>>>();              // it 0 (uniform c)
    k_a<0><<<324, 256>>>();                    // a0
    k_s1<<<dim3(4, GY), 256>>>();              // it 1 (softmax in-block)
    k_a<1><<<324, 256>>>();                    // a1
    k_s_out<<<dim3(4, GY), 256>>>(out);        // it 2 + u_out
    k_vout<<<32, 256>>>(out);                  // v_out
}